// round 2
// baseline (speedup 1.0000x reference)
#include <cuda_runtime.h>
#include <math.h>

#define SEQ   2048
#define DIMM  2048
#define NH    16
#define QLR   512
#define KVLR  512
#define NOPE  128
#define ROPED 64
#define VHD   128
#define QKHD  192          // NOPE + ROPED
#define KVBW  4096         // H * (NOPE + VHD)
#define QW    3072         // H * QKHD
#define EPSV  1.1920929e-07f
#define ATTN_SCALE 0.07216878364870322f   // 192^-0.5

// ---------------- scratch (device globals; no allocation allowed) ----------
__device__ float g_qa  [SEQ * QLR];           // q_a (and rmsnormed in place)
__device__ float g_q   [SEQ * QW];            // q after wq_b (+rope)
__device__ float g_kv  [SEQ * (KVLR + ROPED)];
__device__ float g_kvn [SEQ * KVLR];          // rmsnormed kv latent
__device__ float g_kpe [SEQ * ROPED];         // roped k_pe
__device__ float g_kvb [SEQ * KVBW];          // [s][h][256] : 0..127 k_nope, 128..255 v
__device__ float g_k   [SEQ * NH * QKHD];     // assembled K
__device__ float g_sc  [SEQ * SEQ];           // per-head scores / probs
__device__ float g_att [SEQ * NH * VHD];      // attention output

// ---------------- block reductions ----------------
__device__ __forceinline__ float blockReduceSum(float v) {
    __shared__ float sh[32];
    int lane = threadIdx.x & 31, wid = threadIdx.x >> 5;
    #pragma unroll
    for (int o = 16; o > 0; o >>= 1) v += __shfl_xor_sync(0xffffffffu, v, o);
    if (lane == 0) sh[wid] = v;
    __syncthreads();
    v = (threadIdx.x < (blockDim.x >> 5)) ? sh[threadIdx.x] : 0.f;
    if (wid == 0) {
        #pragma unroll
        for (int o = 16; o > 0; o >>= 1) v += __shfl_xor_sync(0xffffffffu, v, o);
        if (lane == 0) sh[0] = v;
    }
    __syncthreads();
    return sh[0];
}

__device__ __forceinline__ float blockReduceMax(float v) {
    __shared__ float sh[32];
    int lane = threadIdx.x & 31, wid = threadIdx.x >> 5;
    #pragma unroll
    for (int o = 16; o > 0; o >>= 1) v = fmaxf(v, __shfl_xor_sync(0xffffffffu, v, o));
    if (lane == 0) sh[wid] = v;
    __syncthreads();
    v = (threadIdx.x < (blockDim.x >> 5)) ? sh[threadIdx.x] : -INFINITY;
    if (wid == 0) {
        #pragma unroll
        for (int o = 16; o > 0; o >>= 1) v = fmaxf(v, __shfl_xor_sync(0xffffffffu, v, o));
        if (lane == 0) sh[0] = v;
    }
    __syncthreads();
    return sh[0];
}

// ---------------- generic SGEMM-NT: C[M,N] = alpha * A[M,K] @ W[N,K]^T + bias
// 128x128 block tile, BK=8, 8x8 per-thread, 256 threads. K % 8 == 0, M % 128 == 0.
template <bool CAUSAL>
__global__ __launch_bounds__(256)
void gemm_nt(const float* __restrict__ A, int lda,
             const float* __restrict__ W, int ldw,
             const float* __restrict__ bias,
             float* __restrict__ C, int ldc,
             int M, int N, int K, float alpha)
{
    const int BM = 128, BN = 128, BK = 8;
    int m0 = blockIdx.y * BM;
    int n0 = blockIdx.x * BN;
    if (CAUSAL && n0 > m0 + BM - 1) return;   // whole tile above diagonal

    __shared__ float As[BK][BM];
    __shared__ float Ws[BK][BN];

    int tid = threadIdx.x;
    int lr  = tid >> 1;            // 0..127 (row of tile to load)
    int lk  = (tid & 1) * 4;       // 0 or 4 (k offset quad)
    int tx  = tid & 15;            // 0..15 -> 8 output columns
    int ty  = tid >> 4;            // 0..15 -> 8 output rows

    float acc[8][8];
    #pragma unroll
    for (int i = 0; i < 8; i++)
        #pragma unroll
        for (int j = 0; j < 8; j++) acc[i][j] = 0.f;

    for (int k0 = 0; k0 < K; k0 += BK) {
        float4 av = *reinterpret_cast<const float4*>(A + (size_t)(m0 + lr) * lda + k0 + lk);
        As[lk + 0][lr] = av.x; As[lk + 1][lr] = av.y;
        As[lk + 2][lr] = av.z; As[lk + 3][lr] = av.w;

        float4 wv = make_float4(0.f, 0.f, 0.f, 0.f);
        if (n0 + lr < N)
            wv = *reinterpret_cast<const float4*>(W + (size_t)(n0 + lr) * ldw + k0 + lk);
        Ws[lk + 0][lr] = wv.x; Ws[lk + 1][lr] = wv.y;
        Ws[lk + 2][lr] = wv.z; Ws[lk + 3][lr] = wv.w;
        __syncthreads();

        #pragma unroll
        for (int kk = 0; kk < BK; kk++) {
            float a[8], b[8];
            #pragma unroll
            for (int i = 0; i < 8; i++) a[i] = As[kk][ty * 8 + i];
            #pragma unroll
            for (int j = 0; j < 8; j++) b[j] = Ws[kk][tx * 8 + j];
            #pragma unroll
            for (int i = 0; i < 8; i++)
                #pragma unroll
                for (int j = 0; j < 8; j++)
                    acc[i][j] = fmaf(a[i], b[j], acc[i][j]);
        }
        __syncthreads();
    }

    #pragma unroll
    for (int i = 0; i < 8; i++) {
        int row = m0 + ty * 8 + i;
        #pragma unroll
        for (int j = 0; j < 8; j++) {
            int col = n0 + tx * 8 + j;
            if (col < N) {
                float v = alpha * acc[i][j];
                if (bias) v += bias[col];
                C[(size_t)row * ldc + col] = v;
            }
        }
    }
}

// ---------------- SGEMM-NN: C[M,N] = A[M,K] @ B[K,N]  (probs @ V)
__global__ __launch_bounds__(256)
void gemm_nn(const float* __restrict__ A, int lda,
             const float* __restrict__ B, int ldb,
             float* __restrict__ C, int ldc,
             int M, int N, int K)
{
    const int BM = 128, BN = 128, BK = 8;
    int m0 = blockIdx.y * BM;
    int n0 = blockIdx.x * BN;

    __shared__ float As[BK][BM];
    __shared__ float Bs[BK][BN];

    int tid = threadIdx.x;
    int lr  = tid >> 1;
    int lk  = (tid & 1) * 4;
    int kr  = tid >> 5;            // 0..7
    int c4  = (tid & 31) * 4;      // 0..124
    int tx  = tid & 15;
    int ty  = tid >> 4;

    float acc[8][8];
    #pragma unroll
    for (int i = 0; i < 8; i++)
        #pragma unroll
        for (int j = 0; j < 8; j++) acc[i][j] = 0.f;

    for (int k0 = 0; k0 < K; k0 += BK) {
        float4 av = *reinterpret_cast<const float4*>(A + (size_t)(m0 + lr) * lda + k0 + lk);
        As[lk + 0][lr] = av.x; As[lk + 1][lr] = av.y;
        As[lk + 2][lr] = av.z; As[lk + 3][lr] = av.w;

        float4 bv = make_float4(0.f, 0.f, 0.f, 0.f);
        if (n0 + c4 < N)
            bv = *reinterpret_cast<const float4*>(B + (size_t)(k0 + kr) * ldb + n0 + c4);
        *reinterpret_cast<float4*>(&Bs[kr][c4]) = bv;
        __syncthreads();

        #pragma unroll
        for (int kk = 0; kk < BK; kk++) {
            float a[8], b[8];
            #pragma unroll
            for (int i = 0; i < 8; i++) a[i] = As[kk][ty * 8 + i];
            #pragma unroll
            for (int j = 0; j < 8; j++) b[j] = Bs[kk][tx * 8 + j];
            #pragma unroll
            for (int i = 0; i < 8; i++)
                #pragma unroll
                for (int j = 0; j < 8; j++)
                    acc[i][j] = fmaf(a[i], b[j], acc[i][j]);
        }
        __syncthreads();
    }

    #pragma unroll
    for (int i = 0; i < 8; i++) {
        int row = m0 + ty * 8 + i;
        #pragma unroll
        for (int j = 0; j < 8; j++) {
            int col = n0 + tx * 8 + j;
            if (col < N)
                C[(size_t)row * ldc + col] = acc[i][j];
        }
    }
}

// ---------------- rmsnorm over rows of width `dim` ----------------
__global__ void rmsnorm_rows(const float* __restrict__ x, const float* __restrict__ w,
                             float* __restrict__ y, int dim)
{
    int row = blockIdx.x;
    const float* xr = x + (size_t)row * dim;
    float ss = 0.f;
    for (int i = threadIdx.x; i < dim; i += blockDim.x) { float v = xr[i]; ss += v * v; }
    ss = blockReduceSum(ss);
    float rinv = rsqrtf(ss / dim + EPSV);
    float* yr = y + (size_t)row * dim;
    for (int i = threadIdx.x; i < dim; i += blockDim.x) yr[i] = xr[i] * rinv * w[i];
}

// ---------------- split kv -> rmsnorm(latent) + rope(k_pe) ----------------
__global__ void kv_norm_rope(const float* __restrict__ kv, const float* __restrict__ w,
                             const float* __restrict__ cosT, const float* __restrict__ sinT,
                             float* __restrict__ kvn, float* __restrict__ kpe)
{
    int s = blockIdx.x;
    const float* kr = kv + (size_t)s * (KVLR + ROPED);
    float ss = 0.f;
    for (int i = threadIdx.x; i < KVLR; i += blockDim.x) { float v = kr[i]; ss += v * v; }
    ss = blockReduceSum(ss);
    float rinv = rsqrtf(ss / KVLR + EPSV);
    for (int i = threadIdx.x; i < KVLR; i += blockDim.x)
        kvn[(size_t)s * KVLR + i] = kr[i] * rinv * w[i];
    if (threadIdx.x < ROPED / 2) {
        int i = threadIdx.x;
        float x0 = kr[KVLR + 2 * i], x1 = kr[KVLR + 2 * i + 1];
        float c = cosT[s * (ROPED / 2) + i], sn = sinT[s * (ROPED / 2) + i];
        kpe[(size_t)s * ROPED + 2 * i]     = x0 * c - x1 * sn;
        kpe[(size_t)s * ROPED + 2 * i + 1] = x0 * sn + x1 * c;
    }
}

// ---------------- rope on q_pe (last 64 of each head) ----------------
__global__ void rope_q(float* __restrict__ q, const float* __restrict__ cosT,
                       const float* __restrict__ sinT)
{
    int s = blockIdx.x;
    int h = threadIdx.x >> 5;
    int i = threadIdx.x & 31;
    float* p = q + (size_t)s * QW + h * QKHD + NOPE + 2 * i;
    float x0 = p[0], x1 = p[1];
    float c = cosT[s * (ROPED / 2) + i], sn = sinT[s * (ROPED / 2) + i];
    p[0] = x0 * c - x1 * sn;
    p[1] = x0 * sn + x1 * c;
}

// ---------------- assemble K = [k_nope | k_pe] ----------------
__global__ void build_k(const float* __restrict__ kvb, const float* __restrict__ kpe,
                        float* __restrict__ k)
{
    int idx = blockIdx.x * blockDim.x + threadIdx.x;
    const int total = SEQ * NH * QKHD;
    if (idx >= total) return;
    int j  = idx % QKHD;
    int sh = idx / QKHD;
    int h  = sh % NH;
    int s  = sh / NH;
    k[idx] = (j < NOPE) ? kvb[(size_t)s * KVBW + h * (NOPE + VHD) + j]
                        : kpe[(size_t)s * ROPED + (j - NOPE)];
}

// ---------------- causal row softmax (zeros above diagonal) ----------------
__global__ __launch_bounds__(256)
void softmax_causal(float* __restrict__ scores)
{
    int s = blockIdx.x;
    float* row = scores + (size_t)s * SEQ;
    int L = s + 1;
    float v[8];
    float mx = -INFINITY;
    #pragma unroll
    for (int k = 0; k < 8; k++) {
        int t = threadIdx.x + k * 256;
        v[k] = (t < L) ? row[t] : -INFINITY;
        mx = fmaxf(mx, v[k]);
    }
    mx = blockReduceMax(mx);
    float sum = 0.f;
    #pragma unroll
    for (int k = 0; k < 8; k++) {
        int t = threadIdx.x + k * 256;
        if (t < L) { v[k] = __expf(v[k] - mx); sum += v[k]; }
        else v[k] = 0.f;
    }
    sum = blockReduceSum(sum);
    float inv = 1.f / sum;
    #pragma unroll
    for (int k = 0; k < 8; k++)
        row[threadIdx.x + k * 256] = v[k] * inv;
}

// =====================================================================
extern "C" void kernel_launch(void* const* d_in, const int* in_sizes, int n_in,
                              void* d_out, int out_size)
{
    const float* x       = (const float*)d_in[0];
    const float* cosT    = (const float*)d_in[2];
    const float* sinT    = (const float*)d_in[3];
    const float* wq_a_w  = (const float*)d_in[5];
    const float* wq_a_b  = (const float*)d_in[6];
    const float* q_nw    = (const float*)d_in[7];
    const float* wq_b_w  = (const float*)d_in[8];
    const float* wq_b_b  = (const float*)d_in[9];
    const float* wkv_a_w = (const float*)d_in[10];
    const float* wkv_a_b = (const float*)d_in[11];
    const float* kv_nw   = (const float*)d_in[12];
    const float* wkv_b_w = (const float*)d_in[13];
    const float* wkv_b_b = (const float*)d_in[14];
    const float* wo_w    = (const float*)d_in[15];
    const float* wo_b    = (const float*)d_in[16];
    float* out = (float*)d_out;

    float *qa, *q, *kv, *kvn, *kpe, *kvb, *k, *sc, *att;
    cudaGetSymbolAddress((void**)&qa,  g_qa);
    cudaGetSymbolAddress((void**)&q,   g_q);
    cudaGetSymbolAddress((void**)&kv,  g_kv);
    cudaGetSymbolAddress((void**)&kvn, g_kvn);
    cudaGetSymbolAddress((void**)&kpe, g_kpe);
    cudaGetSymbolAddress((void**)&kvb, g_kvb);
    cudaGetSymbolAddress((void**)&k,   g_k);
    cudaGetSymbolAddress((void**)&sc,  g_sc);
    cudaGetSymbolAddress((void**)&att, g_att);

    // q_a = x @ wq_a^T + b ; rmsnorm
    gemm_nt<false><<<dim3(QLR / 128, SEQ / 128), 256>>>(
        x, DIMM, wq_a_w, DIMM, wq_a_b, qa, QLR, SEQ, QLR, DIMM, 1.f);
    rmsnorm_rows<<<SEQ, 256>>>(qa, q_nw, qa, QLR);

    // q = q_a_n @ wq_b^T + b ; rope
    gemm_nt<false><<<dim3(QW / 128, SEQ / 128), 256>>>(
        qa, QLR, wq_b_w, QLR, wq_b_b, q, QW, SEQ, QW, QLR, 1.f);
    rope_q<<<SEQ, NH * 32>>>(q, cosT, sinT);

    // kv = x @ wkv_a^T + b ; split/norm/rope
    gemm_nt<false><<<dim3((KVLR + ROPED + 127) / 128, SEQ / 128), 256>>>(
        x, DIMM, wkv_a_w, DIMM, wkv_a_b, kv, KVLR + ROPED, SEQ, KVLR + ROPED, DIMM, 1.f);
    kv_norm_rope<<<SEQ, 256>>>(kv, kv_nw, cosT, sinT, kvn, kpe);

    // kvb = kvn @ wkv_b^T + b
    gemm_nt<false><<<dim3(KVBW / 128, SEQ / 128), 256>>>(
        kvn, KVLR, wkv_b_w, KVLR, wkv_b_b, kvb, KVBW, SEQ, KVBW, KVLR, 1.f);

    // K assembly
    build_k<<<(SEQ * NH * QKHD + 255) / 256, 256>>>(kvb, kpe, k);

    // per-head attention: scores -> softmax -> probs @ V
    for (int h = 0; h < NH; h++) {
        gemm_nt<true><<<dim3(SEQ / 128, SEQ / 128), 256>>>(
            q + h * QKHD, QW, k + h * QKHD, QW, nullptr,
            sc, SEQ, SEQ, SEQ, QKHD, ATTN_SCALE);
        softmax_causal<<<SEQ, 256>>>(sc);
        gemm_nn<<<dim3(1, SEQ / 128), 256>>>(
            sc, SEQ, kvb + h * (NOPE + VHD) + NOPE, KVBW,
            att + h * VHD, NH * VHD, SEQ, VHD, SEQ);
    }

    // final projection
    gemm_nt<false><<<dim3(DIMM / 128, SEQ / 128), 256>>>(
        att, NH * VHD, wo_w, NH * VHD, wo_b, out, DIMM, SEQ, DIMM, NH * VHD, 1.f);
}

// round 3
// speedup vs baseline: 2.2768x; 2.2768x over previous
#include <cuda_runtime.h>
#include <mma.h>
#include <math.h>

using namespace nvcuda;

#define SEQ   2048
#define DIMM  2048
#define NH    16
#define QLR   512
#define KVLR  512
#define NOPE  128
#define ROPED 64
#define VHD   128
#define QKHD  192          // NOPE + ROPED
#define KVBW  4096         // H * (NOPE + VHD)
#define QW    3072         // H * QKHD
#define EPSV  1.1920929e-07f
#define ATTN_SCALE 0.07216878364870322f   // 192^-0.5

// ---------------- scratch (device globals; no allocation allowed) ----------
__device__ float g_qa  [SEQ * QLR];
__device__ float g_q   [SEQ * QW];
__device__ float g_kv  [SEQ * (KVLR + ROPED)];
__device__ float g_kvn [SEQ * KVLR];
__device__ float g_kpe [SEQ * ROPED];
__device__ float g_kvb [SEQ * KVBW];          // [s][h][256]: 0..127 k_nope, 128..255 v
__device__ float g_k   [SEQ * NH * QKHD];
__device__ float g_sc  [(size_t)NH * SEQ * SEQ];   // all-head scores/probs (256 MB)
__device__ float g_att [SEQ * NH * VHD];

// ---------------- helpers ----------------
__device__ __forceinline__ void split_tf32(float a, float& hi, float& lo) {
    hi = wmma::__float_to_tf32(a);
    lo = wmma::__float_to_tf32(a - hi);
}

__device__ __forceinline__ float blockReduceSum(float v) {
    __shared__ float sh[32];
    int lane = threadIdx.x & 31, wid = threadIdx.x >> 5;
    #pragma unroll
    for (int o = 16; o > 0; o >>= 1) v += __shfl_xor_sync(0xffffffffu, v, o);
    if (lane == 0) sh[wid] = v;
    __syncthreads();
    v = (threadIdx.x < (blockDim.x >> 5)) ? sh[threadIdx.x] : 0.f;
    if (wid == 0) {
        #pragma unroll
        for (int o = 16; o > 0; o >>= 1) v += __shfl_xor_sync(0xffffffffu, v, o);
        if (lane == 0) sh[0] = v;
    }
    __syncthreads();
    return sh[0];
}

__device__ __forceinline__ float blockReduceMax(float v) {
    __shared__ float sh[32];
    int lane = threadIdx.x & 31, wid = threadIdx.x >> 5;
    #pragma unroll
    for (int o = 16; o > 0; o >>= 1) v = fmaxf(v, __shfl_xor_sync(0xffffffffu, v, o));
    if (lane == 0) sh[wid] = v;
    __syncthreads();
    v = (threadIdx.x < (blockDim.x >> 5)) ? sh[threadIdx.x] : -INFINITY;
    if (wid == 0) {
        #pragma unroll
        for (int o = 16; o > 0; o >>= 1) v = fmaxf(v, __shfl_xor_sync(0xffffffffu, v, o));
        if (lane == 0) sh[0] = v;
    }
    __syncthreads();
    return sh[0];
}

// =====================================================================
// 3xTF32 GEMM-NT: C[M,N] = alpha * A[M,K] @ W[N,K]^T        (batched by z)
// Block 128x128, BK=16, 8 warps, warp tile 32x64 (wmma m16n16k8).
// =====================================================================
template <bool CAUSAL, bool NGUARD>
__global__ __launch_bounds__(256)
void gemm3_nt(const float* __restrict__ A, int lda, long sA,
              const float* __restrict__ W, int ldw, long sW,
              float* __restrict__ C, int ldc, long sC,
              int M, int N, int K, float alpha)
{
    const int BM = 128, BN = 128, BK = 16, LDS = BK + 4;
    int m0 = blockIdx.y * BM;
    int n0 = blockIdx.x * BN;
    if (CAUSAL && n0 > m0) return;
    long z = blockIdx.z;
    A += z * sA; W += z * sW; C += z * sC;

    __shared__ float Ah[BM][LDS], Al[BM][LDS], Wh[BN][LDS], Wl[BN][LDS];

    int tid = threadIdx.x;
    int wid = tid >> 5;
    int wr = (wid & 3) * 32;
    int wc = (wid >> 2) * 64;

    wmma::fragment<wmma::accumulator, 16, 16, 8, float> acc[2][4];
    #pragma unroll
    for (int i = 0; i < 2; i++)
        #pragma unroll
        for (int j = 0; j < 4; j++) wmma::fill_fragment(acc[i][j], 0.f);

    int lrow = tid >> 1;
    int lc0  = (tid & 1) * 8;

    for (int k0 = 0; k0 < K; k0 += BK) {
        {   // A tile
            const float* p = A + (size_t)(m0 + lrow) * lda + k0 + lc0;
            float4 v0 = *reinterpret_cast<const float4*>(p);
            float4 v1 = *reinterpret_cast<const float4*>(p + 4);
            float vv[8] = {v0.x, v0.y, v0.z, v0.w, v1.x, v1.y, v1.z, v1.w};
            #pragma unroll
            for (int i = 0; i < 8; i++) {
                float hi, lo; split_tf32(vv[i], hi, lo);
                Ah[lrow][lc0 + i] = hi;
                Al[lrow][lc0 + i] = lo;
            }
        }
        {   // W tile
            float vv[8] = {0, 0, 0, 0, 0, 0, 0, 0};
            if (!NGUARD || (n0 + lrow) < N) {
                const float* p = W + (size_t)(n0 + lrow) * ldw + k0 + lc0;
                float4 v0 = *reinterpret_cast<const float4*>(p);
                float4 v1 = *reinterpret_cast<const float4*>(p + 4);
                vv[0] = v0.x; vv[1] = v0.y; vv[2] = v0.z; vv[3] = v0.w;
                vv[4] = v1.x; vv[5] = v1.y; vv[6] = v1.z; vv[7] = v1.w;
            }
            #pragma unroll
            for (int i = 0; i < 8; i++) {
                float hi, lo; split_tf32(vv[i], hi, lo);
                Wh[lrow][lc0 + i] = hi;
                Wl[lrow][lc0 + i] = lo;
            }
        }
        __syncthreads();

        #pragma unroll
        for (int kk = 0; kk < BK; kk += 8) {
            wmma::fragment<wmma::matrix_a, 16, 16, 8, wmma::precision::tf32, wmma::row_major> ah[2], al[2];
            wmma::fragment<wmma::matrix_b, 16, 16, 8, wmma::precision::tf32, wmma::col_major> bh[4], bl[4];
            #pragma unroll
            for (int i = 0; i < 2; i++) {
                wmma::load_matrix_sync(ah[i], &Ah[wr + i * 16][kk], LDS);
                wmma::load_matrix_sync(al[i], &Al[wr + i * 16][kk], LDS);
            }
            #pragma unroll
            for (int j = 0; j < 4; j++) {
                wmma::load_matrix_sync(bh[j], &Wh[wc + j * 16][kk], LDS);
                wmma::load_matrix_sync(bl[j], &Wl[wc + j * 16][kk], LDS);
            }
            #pragma unroll
            for (int i = 0; i < 2; i++)
                #pragma unroll
                for (int j = 0; j < 4; j++) {
                    wmma::mma_sync(acc[i][j], ah[i], bh[j], acc[i][j]);
                    wmma::mma_sync(acc[i][j], al[i], bh[j], acc[i][j]);
                    wmma::mma_sync(acc[i][j], ah[i], bl[j], acc[i][j]);
                }
        }
        __syncthreads();
    }

    #pragma unroll
    for (int i = 0; i < 2; i++)
        #pragma unroll
        for (int j = 0; j < 4; j++) {
            int col = n0 + wc + j * 16;
            if (NGUARD && col >= N) continue;
            if (alpha != 1.f) {
                #pragma unroll
                for (int t = 0; t < acc[i][j].num_elements; t++) acc[i][j].x[t] *= alpha;
            }
            wmma::store_matrix_sync(&C[(size_t)(m0 + wr + i * 16) * ldc + col],
                                    acc[i][j], ldc, wmma::mem_row_major);
        }
}

// =====================================================================
// 3xTF32 GEMM-NN: C[M,N] = A[M,K] @ B[K,N]   (batched by z, causal k-limit)
// B tile stored transposed in smem so wmma matrix_b is col_major.
// N must equal 128 (BN). Used for probs @ V.
// =====================================================================
template <bool CAUSALK>
__global__ __launch_bounds__(256)
void gemm3_nn(const float* __restrict__ A, int lda, long sA,
              const float* __restrict__ B, int ldb, long sB,
              float* __restrict__ C, int ldc, long sC,
              int M, int N, int K)
{
    const int BM = 128, BN = 128, BK = 16, LDS = BK + 4;
    int m0 = blockIdx.y * BM;
    int n0 = blockIdx.x * BN;
    long z = blockIdx.z;
    A += z * sA; B += z * sB; C += z * sC;

    int kmax = CAUSALK ? min(K, m0 + BM) : K;

    __shared__ float Ah[BM][LDS], Al[BM][LDS], Bh[BN][LDS], Bl[BN][LDS];

    int tid = threadIdx.x;
    int wid = tid >> 5;
    int wr = (wid & 3) * 32;
    int wc = (wid >> 2) * 64;

    wmma::fragment<wmma::accumulator, 16, 16, 8, float> acc[2][4];
    #pragma unroll
    for (int i = 0; i < 2; i++)
        #pragma unroll
        for (int j = 0; j < 4; j++) wmma::fill_fragment(acc[i][j], 0.f);

    int lrow = tid >> 1;
    int lc0  = (tid & 1) * 8;
    int bkr  = tid >> 4;          // 0..15 (k row)
    int bc   = tid & 15;          // n column base (strided by 16)

    for (int k0 = 0; k0 < kmax; k0 += BK) {
        {   // A tile
            const float* p = A + (size_t)(m0 + lrow) * lda + k0 + lc0;
            float4 v0 = *reinterpret_cast<const float4*>(p);
            float4 v1 = *reinterpret_cast<const float4*>(p + 4);
            float vv[8] = {v0.x, v0.y, v0.z, v0.w, v1.x, v1.y, v1.z, v1.w};
            #pragma unroll
            for (int i = 0; i < 8; i++) {
                float hi, lo; split_tf32(vv[i], hi, lo);
                Ah[lrow][lc0 + i] = hi;
                Al[lrow][lc0 + i] = lo;
            }
        }
        {   // B tile (transpose into smem: Bh[n][k] = B[k0+k][n0+n])
            const float* p = B + (size_t)(k0 + bkr) * ldb + n0 + bc;
            #pragma unroll
            for (int i = 0; i < 8; i++) {
                int n = bc + 16 * i;
                float hi, lo; split_tf32(p[16 * i], hi, lo);
                Bh[n][bkr] = hi;
                Bl[n][bkr] = lo;
            }
        }
        __syncthreads();

        #pragma unroll
        for (int kk = 0; kk < BK; kk += 8) {
            wmma::fragment<wmma::matrix_a, 16, 16, 8, wmma::precision::tf32, wmma::row_major> ah[2], al[2];
            wmma::fragment<wmma::matrix_b, 16, 16, 8, wmma::precision::tf32, wmma::col_major> bh[4], bl[4];
            #pragma unroll
            for (int i = 0; i < 2; i++) {
                wmma::load_matrix_sync(ah[i], &Ah[wr + i * 16][kk], LDS);
                wmma::load_matrix_sync(al[i], &Al[wr + i * 16][kk], LDS);
            }
            #pragma unroll
            for (int j = 0; j < 4; j++) {
                wmma::load_matrix_sync(bh[j], &Bh[wc + j * 16][kk], LDS);
                wmma::load_matrix_sync(bl[j], &Bl[wc + j * 16][kk], LDS);
            }
            #pragma unroll
            for (int i = 0; i < 2; i++)
                #pragma unroll
                for (int j = 0; j < 4; j++) {
                    wmma::mma_sync(acc[i][j], ah[i], bh[j], acc[i][j]);
                    wmma::mma_sync(acc[i][j], al[i], bh[j], acc[i][j]);
                    wmma::mma_sync(acc[i][j], ah[i], bl[j], acc[i][j]);
                }
        }
        __syncthreads();
    }

    #pragma unroll
    for (int i = 0; i < 2; i++)
        #pragma unroll
        for (int j = 0; j < 4; j++) {
            int col = n0 + wc + j * 16;
            wmma::store_matrix_sync(&C[(size_t)(m0 + wr + i * 16) * ldc + col],
                                    acc[i][j], ldc, wmma::mem_row_major);
        }
}

// ---------------- bias add (row-broadcast) ----------------
__global__ void add_bias(float* __restrict__ C, const float* __restrict__ bias,
                         int N, int total4)
{
    int i = blockIdx.x * blockDim.x + threadIdx.x;
    if (i >= total4) return;
    float4* p = reinterpret_cast<float4*>(C) + i;
    float4 v = *p;
    int col = (i * 4) % N;
    v.x += bias[col];
    v.y += bias[col + 1];
    v.z += bias[col + 2];
    v.w += bias[col + 3];
    *p = v;
}

// ---------------- rmsnorm over rows ----------------
__global__ void rmsnorm_rows(const float* __restrict__ x, const float* __restrict__ w,
                             float* __restrict__ y, int dim)
{
    int row = blockIdx.x;
    const float* xr = x + (size_t)row * dim;
    float ss = 0.f;
    for (int i = threadIdx.x; i < dim; i += blockDim.x) { float v = xr[i]; ss += v * v; }
    ss = blockReduceSum(ss);
    float rinv = rsqrtf(ss / dim + EPSV);
    float* yr = y + (size_t)row * dim;
    for (int i = threadIdx.x; i < dim; i += blockDim.x) yr[i] = xr[i] * rinv * w[i];
}

// ---------------- split kv -> rmsnorm(latent) + rope(k_pe) ----------------
__global__ void kv_norm_rope(const float* __restrict__ kv, const float* __restrict__ w,
                             const float* __restrict__ cosT, const float* __restrict__ sinT,
                             float* __restrict__ kvn, float* __restrict__ kpe)
{
    int s = blockIdx.x;
    const float* kr = kv + (size_t)s * (KVLR + ROPED);
    float ss = 0.f;
    for (int i = threadIdx.x; i < KVLR; i += blockDim.x) { float v = kr[i]; ss += v * v; }
    ss = blockReduceSum(ss);
    float rinv = rsqrtf(ss / KVLR + EPSV);
    for (int i = threadIdx.x; i < KVLR; i += blockDim.x)
        kvn[(size_t)s * KVLR + i] = kr[i] * rinv * w[i];
    if (threadIdx.x < ROPED / 2) {
        int i = threadIdx.x;
        float x0 = kr[KVLR + 2 * i], x1 = kr[KVLR + 2 * i + 1];
        float c = cosT[s * (ROPED / 2) + i], sn = sinT[s * (ROPED / 2) + i];
        kpe[(size_t)s * ROPED + 2 * i]     = x0 * c - x1 * sn;
        kpe[(size_t)s * ROPED + 2 * i + 1] = x0 * sn + x1 * c;
    }
}

// ---------------- rope on q_pe ----------------
__global__ void rope_q(float* __restrict__ q, const float* __restrict__ cosT,
                       const float* __restrict__ sinT)
{
    int s = blockIdx.x;
    int h = threadIdx.x >> 5;
    int i = threadIdx.x & 31;
    float* p = q + (size_t)s * QW + h * QKHD + NOPE + 2 * i;
    float x0 = p[0], x1 = p[1];
    float c = cosT[s * (ROPED / 2) + i], sn = sinT[s * (ROPED / 2) + i];
    p[0] = x0 * c - x1 * sn;
    p[1] = x0 * sn + x1 * c;
}

// ---------------- assemble K = [k_nope | k_pe] ----------------
__global__ void build_k(const float* __restrict__ kvb, const float* __restrict__ kpe,
                        float* __restrict__ k)
{
    int idx = blockIdx.x * blockDim.x + threadIdx.x;
    const int total = SEQ * NH * QKHD;
    if (idx >= total) return;
    int j  = idx % QKHD;
    int sh = idx / QKHD;
    int h  = sh % NH;
    int s  = sh / NH;
    k[idx] = (j < NOPE) ? kvb[(size_t)s * KVBW + h * (NOPE + VHD) + j]
                        : kpe[(size_t)s * ROPED + (j - NOPE)];
}

// ---------------- causal row softmax, batched over heads ----------------
__global__ __launch_bounds__(256)
void softmax_causal(float* __restrict__ scores)
{
    int s = blockIdx.x;
    int h = blockIdx.y;
    float* row = scores + ((size_t)h * SEQ + s) * SEQ;
    int L = s + 1;
    float v[8];
    float mx = -INFINITY;
    #pragma unroll
    for (int k = 0; k < 8; k++) {
        int t = threadIdx.x + k * 256;
        v[k] = (t < L) ? row[t] : -INFINITY;
        mx = fmaxf(mx, v[k]);
    }
    mx = blockReduceMax(mx);
    float sum = 0.f;
    #pragma unroll
    for (int k = 0; k < 8; k++) {
        int t = threadIdx.x + k * 256;
        if (t < L) { v[k] = __expf(v[k] - mx); sum += v[k]; }
        else v[k] = 0.f;
    }
    sum = blockReduceSum(sum);
    float inv = 1.f / sum;
    #pragma unroll
    for (int k = 0; k < 8; k++)
        row[threadIdx.x + k * 256] = v[k] * inv;
}

// =====================================================================
extern "C" void kernel_launch(void* const* d_in, const int* in_sizes, int n_in,
                              void* d_out, int out_size)
{
    const float* x       = (const float*)d_in[0];
    const float* cosT    = (const float*)d_in[2];
    const float* sinT    = (const float*)d_in[3];
    const float* wq_a_w  = (const float*)d_in[5];
    const float* wq_a_b  = (const float*)d_in[6];
    const float* q_nw    = (const float*)d_in[7];
    const float* wq_b_w  = (const float*)d_in[8];
    const float* wq_b_b  = (const float*)d_in[9];
    const float* wkv_a_w = (const float*)d_in[10];
    const float* wkv_a_b = (const float*)d_in[11];
    const float* kv_nw   = (const float*)d_in[12];
    const float* wkv_b_w = (const float*)d_in[13];
    const float* wkv_b_b = (const float*)d_in[14];
    const float* wo_w    = (const float*)d_in[15];
    const float* wo_b    = (const float*)d_in[16];
    float* out = (float*)d_out;

    float *qa, *q, *kv, *kvn, *kpe, *kvb, *k, *sc, *att;
    cudaGetSymbolAddress((void**)&qa,  g_qa);
    cudaGetSymbolAddress((void**)&q,   g_q);
    cudaGetSymbolAddress((void**)&kv,  g_kv);
    cudaGetSymbolAddress((void**)&kvn, g_kvn);
    cudaGetSymbolAddress((void**)&kpe, g_kpe);
    cudaGetSymbolAddress((void**)&kvb, g_kvb);
    cudaGetSymbolAddress((void**)&k,   g_k);
    cudaGetSymbolAddress((void**)&sc,  g_sc);
    cudaGetSymbolAddress((void**)&att, g_att);

    // ---- q_a = x @ wq_a^T + b ; rmsnorm ----
    gemm3_nt<false, false><<<dim3(QLR / 128, SEQ / 128, 1), 256>>>(
        x, DIMM, 0, wq_a_w, DIMM, 0, qa, QLR, 0, SEQ, QLR, DIMM, 1.f);
    add_bias<<<(SEQ * QLR / 4 + 255) / 256, 256>>>(qa, wq_a_b, QLR, SEQ * QLR / 4);
    rmsnorm_rows<<<SEQ, 256>>>(qa, q_nw, qa, QLR);

    // ---- q = qa_n @ wq_b^T + b ; rope ----
    gemm3_nt<false, false><<<dim3(QW / 128, SEQ / 128, 1), 256>>>(
        qa, QLR, 0, wq_b_w, QLR, 0, q, QW, 0, SEQ, QW, QLR, 1.f);
    add_bias<<<(SEQ * QW / 4 + 255) / 256, 256>>>(q, wq_b_b, QW, SEQ * QW / 4);
    rope_q<<<SEQ, NH * 32>>>(q, cosT, sinT);

    // ---- kv = x @ wkv_a^T + b ; split/norm/rope ----
    gemm3_nt<false, true><<<dim3((KVLR + ROPED + 127) / 128, SEQ / 128, 1), 256>>>(
        x, DIMM, 0, wkv_a_w, DIMM, 0, kv, KVLR + ROPED, 0, SEQ, KVLR + ROPED, DIMM, 1.f);
    add_bias<<<(SEQ * (KVLR + ROPED) / 4 + 255) / 256, 256>>>(
        kv, wkv_a_b, KVLR + ROPED, SEQ * (KVLR + ROPED) / 4);
    kv_norm_rope<<<SEQ, 256>>>(kv, kv_nw, cosT, sinT, kvn, kpe);

    // ---- kvb = kvn @ wkv_b^T + b ----
    gemm3_nt<false, false><<<dim3(KVBW / 128, SEQ / 128, 1), 256>>>(
        kvn, KVLR, 0, wkv_b_w, KVLR, 0, kvb, KVBW, 0, SEQ, KVBW, KVLR, 1.f);
    add_bias<<<(SEQ * KVBW / 4 + 255) / 256, 256>>>(kvb, wkv_b_b, KVBW, SEQ * KVBW / 4);

    // ---- assemble K ----
    build_k<<<(SEQ * NH * QKHD + 255) / 256, 256>>>(kvb, kpe, k);

    // ---- scores (batched over heads, causal tile-skip) ----
    gemm3_nt<true, false><<<dim3(SEQ / 128, SEQ / 128, NH), 256>>>(
        q, QW, QKHD, k, QW, QKHD, sc, SEQ, (long)SEQ * SEQ,
        SEQ, SEQ, QKHD, ATTN_SCALE);

    // ---- softmax (batched) ----
    softmax_causal<<<dim3(SEQ, NH), 256>>>(sc);

    // ---- att = probs @ V (batched, causal K-limit) ----
    gemm3_nn<true><<<dim3(1, SEQ / 128, NH), 256>>>(
        sc, SEQ, (long)SEQ * SEQ,
        kvb + NOPE, KVBW, (long)(NOPE + VHD),
        att, NH * VHD, (long)VHD,
        SEQ, VHD, SEQ);

    // ---- out = att @ wo^T + b ----
    gemm3_nt<false, false><<<dim3(DIMM / 128, SEQ / 128, 1), 256>>>(
        att, NH * VHD, 0, wo_w, NH * VHD, 0, out, DIMM, 0, SEQ, DIMM, NH * VHD, 1.f);
    add_bias<<<(SEQ * DIMM / 4 + 255) / 256, 256>>>(out, wo_b, DIMM, SEQ * DIMM / 4);
}

// round 5
// speedup vs baseline: 2.6768x; 1.1757x over previous
#include <cuda_runtime.h>
#include <mma.h>
#include <math.h>

using namespace nvcuda;

#define SEQ   2048
#define DIMM  2048
#define NH    16
#define QLR   512
#define KVLR  512
#define NOPE  128
#define ROPED 64
#define VHD   128
#define QKHD  192
#define KVBW  4096
#define QW    3072
#define EPSV  1.1920929e-07f
#define ATTN_SCALE 0.07216878364870322f   // 192^-0.5

#define LDS   20                   // BK(16)+4 padding
#define GEMM_SMEM (8 * 128 * LDS * 4)   // 2 buf * 4 arrays * 128 * LDS floats = 81920 B
#define STG_LD 132                 // staging leading dim

// ---------------- scratch ----------------
__device__ float g_qa  [SEQ * QLR];
__device__ float g_q   [SEQ * QW];
__device__ float g_kv  [SEQ * (KVLR + ROPED)];
__device__ float g_kvn [SEQ * KVLR];
__device__ float g_kpe [SEQ * ROPED];
__device__ float g_kvb [SEQ * KVBW];
__device__ float g_k   [SEQ * NH * QKHD];
__device__ float g_sc  [(size_t)NH * SEQ * SEQ];
__device__ float g_att [SEQ * NH * VHD];

__device__ __forceinline__ void split_tf32(float a, float& hi, float& lo) {
    hi = wmma::__float_to_tf32(a);
    lo = wmma::__float_to_tf32(a - hi);
}

__device__ __forceinline__ float blockReduceSum(float v) {
    __shared__ float sh[32];
    int lane = threadIdx.x & 31, wid = threadIdx.x >> 5;
    #pragma unroll
    for (int o = 16; o > 0; o >>= 1) v += __shfl_xor_sync(0xffffffffu, v, o);
    if (lane == 0) sh[wid] = v;
    __syncthreads();
    v = (threadIdx.x < (blockDim.x >> 5)) ? sh[threadIdx.x] : 0.f;
    if (wid == 0) {
        #pragma unroll
        for (int o = 16; o > 0; o >>= 1) v += __shfl_xor_sync(0xffffffffu, v, o);
        if (lane == 0) sh[0] = v;
    }
    __syncthreads();
    return sh[0];
}

__device__ __forceinline__ float blockReduceMax(float v) {
    __shared__ float sh[32];
    int lane = threadIdx.x & 31, wid = threadIdx.x >> 5;
    #pragma unroll
    for (int o = 16; o > 0; o >>= 1) v = fmaxf(v, __shfl_xor_sync(0xffffffffu, v, o));
    if (lane == 0) sh[wid] = v;
    __syncthreads();
    v = (threadIdx.x < (blockDim.x >> 5)) ? sh[threadIdx.x] : -INFINITY;
    if (wid == 0) {
        #pragma unroll
        for (int o = 16; o > 0; o >>= 1) v = fmaxf(v, __shfl_xor_sync(0xffffffffu, v, o));
        if (lane == 0) sh[0] = v;
    }
    __syncthreads();
    return sh[0];
}

// =====================================================================
// 3xTF32 GEMM-NT, double-buffered, fused alpha+bias epilogue.
// C[M,N] = alpha * A[M,K] @ W[N,K]^T + bias   (batched over blockIdx.z)
// =====================================================================
template <bool CAUSAL, bool NGUARD>
__global__ __launch_bounds__(256)
void gemm3_nt(const float* __restrict__ A, int lda, long sA,
              const float* __restrict__ W, int ldw, long sW,
              const float* __restrict__ bias,
              float* __restrict__ C, int ldc, long sC,
              int M, int N, int K, float alpha)
{
    const int BM = 128, BN = 128, BK = 16;
    extern __shared__ float sm[];
    const int REG = 128 * LDS;            // floats per (buffer, array)
    float* AH = sm;                        // [2][REG]
    float* AL = sm + 2 * REG;
    float* WH = sm + 4 * REG;
    float* WL = sm + 6 * REG;

    int m0 = blockIdx.y * BM;
    int n0 = blockIdx.x * BN;
    if (CAUSAL && n0 > m0) return;
    long z = blockIdx.z;
    A += z * sA; W += z * sW; C += z * sC;

    int tid = threadIdx.x;
    int wid = tid >> 5;
    int wr = (wid & 3) * 32;
    int wc = (wid >> 2) * 64;
    int lrow = tid >> 1;
    int lc0  = (tid & 1) * 8;

    const float* pAg = A + (size_t)(m0 + lrow) * lda + lc0;
    const float* pWg = W + (size_t)(n0 + lrow) * ldw + lc0;
    bool wvalid = !NGUARD || (n0 + lrow) < N;

    wmma::fragment<wmma::accumulator, 16, 16, 8, float> acc[2][4];
    #pragma unroll
    for (int i = 0; i < 2; i++)
        #pragma unroll
        for (int j = 0; j < 4; j++) wmma::fill_fragment(acc[i][j], 0.f);

    float ra[8], rw[8];

    // prologue: tile 0
    {
        float4 a0 = *reinterpret_cast<const float4*>(pAg);
        float4 a1 = *reinterpret_cast<const float4*>(pAg + 4);
        ra[0]=a0.x; ra[1]=a0.y; ra[2]=a0.z; ra[3]=a0.w;
        ra[4]=a1.x; ra[5]=a1.y; ra[6]=a1.z; ra[7]=a1.w;
        if (wvalid) {
            float4 w0 = *reinterpret_cast<const float4*>(pWg);
            float4 w1 = *reinterpret_cast<const float4*>(pWg + 4);
            rw[0]=w0.x; rw[1]=w0.y; rw[2]=w0.z; rw[3]=w0.w;
            rw[4]=w1.x; rw[5]=w1.y; rw[6]=w1.z; rw[7]=w1.w;
        } else {
            #pragma unroll
            for (int i = 0; i < 8; i++) rw[i] = 0.f;
        }
        int off = lrow * LDS + lc0;
        #pragma unroll
        for (int i = 0; i < 8; i++) {
            float hi, lo;
            split_tf32(ra[i], hi, lo); AH[off + i] = hi; AL[off + i] = lo;
            split_tf32(rw[i], hi, lo); WH[off + i] = hi; WL[off + i] = lo;
        }
    }
    __syncthreads();

    int nt = K / BK;
    for (int t = 0; t < nt; t++) {
        int b = (t & 1) * REG;
        if (t + 1 < nt) {   // prefetch next tile
            int k0 = (t + 1) * BK;
            float4 a0 = *reinterpret_cast<const float4*>(pAg + k0);
            float4 a1 = *reinterpret_cast<const float4*>(pAg + k0 + 4);
            ra[0]=a0.x; ra[1]=a0.y; ra[2]=a0.z; ra[3]=a0.w;
            ra[4]=a1.x; ra[5]=a1.y; ra[6]=a1.z; ra[7]=a1.w;
            if (wvalid) {
                float4 w0 = *reinterpret_cast<const float4*>(pWg + k0);
                float4 w1 = *reinterpret_cast<const float4*>(pWg + k0 + 4);
                rw[0]=w0.x; rw[1]=w0.y; rw[2]=w0.z; rw[3]=w0.w;
                rw[4]=w1.x; rw[5]=w1.y; rw[6]=w1.z; rw[7]=w1.w;
            } else {
                #pragma unroll
                for (int i = 0; i < 8; i++) rw[i] = 0.f;
            }
        }

        #pragma unroll
        for (int kk = 0; kk < BK; kk += 8) {
            wmma::fragment<wmma::matrix_a, 16, 16, 8, wmma::precision::tf32, wmma::row_major> ah[2], al[2];
            wmma::fragment<wmma::matrix_b, 16, 16, 8, wmma::precision::tf32, wmma::col_major> bh[4], bl[4];
            #pragma unroll
            for (int i = 0; i < 2; i++) {
                wmma::load_matrix_sync(ah[i], AH + b + (wr + i * 16) * LDS + kk, LDS);
                wmma::load_matrix_sync(al[i], AL + b + (wr + i * 16) * LDS + kk, LDS);
            }
            #pragma unroll
            for (int j = 0; j < 4; j++) {
                wmma::load_matrix_sync(bh[j], WH + b + (wc + j * 16) * LDS + kk, LDS);
                wmma::load_matrix_sync(bl[j], WL + b + (wc + j * 16) * LDS + kk, LDS);
            }
            #pragma unroll
            for (int i = 0; i < 2; i++)
                #pragma unroll
                for (int j = 0; j < 4; j++) {
                    wmma::mma_sync(acc[i][j], ah[i], bh[j], acc[i][j]);
                    wmma::mma_sync(acc[i][j], al[i], bh[j], acc[i][j]);
                    wmma::mma_sync(acc[i][j], ah[i], bl[j], acc[i][j]);
                }
        }

        if (t + 1 < nt) {
            int nb = ((t + 1) & 1) * REG;
            int off = lrow * LDS + lc0;
            #pragma unroll
            for (int i = 0; i < 8; i++) {
                float hi, lo;
                split_tf32(ra[i], hi, lo); AH[nb + off + i] = hi; AL[nb + off + i] = lo;
                split_tf32(rw[i], hi, lo); WH[nb + off + i] = hi; WL[nb + off + i] = lo;
            }
        }
        __syncthreads();
    }

    // epilogue: stage accumulators to smem, read back coalesced with alpha+bias
    float* stg = sm;
    #pragma unroll
    for (int i = 0; i < 2; i++)
        #pragma unroll
        for (int j = 0; j < 4; j++)
            wmma::store_matrix_sync(stg + (wr + i * 16) * STG_LD + wc + j * 16,
                                    acc[i][j], STG_LD, wmma::mem_row_major);
    __syncthreads();

    int c4 = (tid & 31);
    int col = n0 + c4 * 4;
    float4 bv = make_float4(0.f, 0.f, 0.f, 0.f);
    bool cval = !NGUARD || col + 3 < N;
    if (bias && cval) {
        bv.x = bias[col]; bv.y = bias[col + 1];
        bv.z = bias[col + 2]; bv.w = bias[col + 3];
    }
    #pragma unroll
    for (int rr = 0; rr < 16; rr++) {
        int row = (tid >> 5) + rr * 8;
        float4 v = *reinterpret_cast<float4*>(stg + row * STG_LD + c4 * 4);
        v.x = v.x * alpha + bv.x;
        v.y = v.y * alpha + bv.y;
        v.z = v.z * alpha + bv.z;
        v.w = v.w * alpha + bv.w;
        if (cval) {
            *reinterpret_cast<float4*>(C + (size_t)(m0 + row) * ldc + col) = v;
        } else if (NGUARD) {
            float vv[4] = {v.x, v.y, v.z, v.w};
            for (int e = 0; e < 4; e++)
                if (col + e < N)
                    C[(size_t)(m0 + row) * ldc + col + e] = vv[e] + (bias ? bias[col + e] : 0.f);
        }
    }
}

// =====================================================================
// 3xTF32 GEMM-NN, double-buffered: C[M,128] = A[M,K] @ B[K,128]
// (batched over z; causal k-limit). Used for probs @ V.
// =====================================================================
template <bool CAUSALK>
__global__ __launch_bounds__(256)
void gemm3_nn(const float* __restrict__ A, int lda, long sA,
              const float* __restrict__ B, int ldb, long sB,
              float* __restrict__ C, int ldc, long sC,
              int M, int K)
{
    const int BM = 128, BK = 16;
    extern __shared__ float sm[];
    const int REG = 128 * LDS;
    float* AH = sm;
    float* AL = sm + 2 * REG;
    float* BH = sm + 4 * REG;
    float* BL = sm + 6 * REG;

    int m0 = blockIdx.y * BM;
    long z = blockIdx.z;
    A += z * sA; B += z * sB; C += z * sC;

    int kmax = CAUSALK ? min(K, m0 + BM) : K;

    int tid = threadIdx.x;
    int wid = tid >> 5;
    int wr = (wid & 3) * 32;
    int wc = (wid >> 2) * 64;
    int lrow = tid >> 1;
    int lc0  = (tid & 1) * 8;
    int bkr  = tid >> 4;          // 0..15
    int bc   = tid & 15;          // col base

    const float* pAg = A + (size_t)(m0 + lrow) * lda + lc0;
    const float* pBg = B + (size_t)bkr * ldb + bc;

    wmma::fragment<wmma::accumulator, 16, 16, 8, float> acc[2][4];
    #pragma unroll
    for (int i = 0; i < 2; i++)
        #pragma unroll
        for (int j = 0; j < 4; j++) wmma::fill_fragment(acc[i][j], 0.f);

    float ra[8], rb[8];

    // prologue
    {
        float4 a0 = *reinterpret_cast<const float4*>(pAg);
        float4 a1 = *reinterpret_cast<const float4*>(pAg + 4);
        ra[0]=a0.x; ra[1]=a0.y; ra[2]=a0.z; ra[3]=a0.w;
        ra[4]=a1.x; ra[5]=a1.y; ra[6]=a1.z; ra[7]=a1.w;
        #pragma unroll
        for (int i = 0; i < 8; i++) rb[i] = pBg[16 * i];
        int off = lrow * LDS + lc0;
        #pragma unroll
        for (int i = 0; i < 8; i++) {
            float hi, lo;
            split_tf32(ra[i], hi, lo); AH[off + i] = hi; AL[off + i] = lo;
            split_tf32(rb[i], hi, lo);
            BH[(bc + 16 * i) * LDS + bkr] = hi;
            BL[(bc + 16 * i) * LDS + bkr] = lo;
        }
    }
    __syncthreads();

    int nt = kmax / BK;
    for (int t = 0; t < nt; t++) {
        int b = (t & 1) * REG;
        if (t + 1 < nt) {
            int k0 = (t + 1) * BK;
            float4 a0 = *reinterpret_cast<const float4*>(pAg + k0);
            float4 a1 = *reinterpret_cast<const float4*>(pAg + k0 + 4);
            ra[0]=a0.x; ra[1]=a0.y; ra[2]=a0.z; ra[3]=a0.w;
            ra[4]=a1.x; ra[5]=a1.y; ra[6]=a1.z; ra[7]=a1.w;
            const float* p = pBg + (size_t)k0 * ldb;
            #pragma unroll
            for (int i = 0; i < 8; i++) rb[i] = p[16 * i];
        }

        #pragma unroll
        for (int kk = 0; kk < BK; kk += 8) {
            wmma::fragment<wmma::matrix_a, 16, 16, 8, wmma::precision::tf32, wmma::row_major> ah[2], al[2];
            wmma::fragment<wmma::matrix_b, 16, 16, 8, wmma::precision::tf32, wmma::col_major> bh[4], bl[4];
            #pragma unroll
            for (int i = 0; i < 2; i++) {
                wmma::load_matrix_sync(ah[i], AH + b + (wr + i * 16) * LDS + kk, LDS);
                wmma::load_matrix_sync(al[i], AL + b + (wr + i * 16) * LDS + kk, LDS);
            }
            #pragma unroll
            for (int j = 0; j < 4; j++) {
                wmma::load_matrix_sync(bh[j], BH + b + (wc + j * 16) * LDS + kk, LDS);
                wmma::load_matrix_sync(bl[j], BL + b + (wc + j * 16) * LDS + kk, LDS);
            }
            #pragma unroll
            for (int i = 0; i < 2; i++)
                #pragma unroll
                for (int j = 0; j < 4; j++) {
                    wmma::mma_sync(acc[i][j], ah[i], bh[j], acc[i][j]);
                    wmma::mma_sync(acc[i][j], al[i], bh[j], acc[i][j]);
                    wmma::mma_sync(acc[i][j], ah[i], bl[j], acc[i][j]);
                }
        }

        if (t + 1 < nt) {
            int nb = ((t + 1) & 1) * REG;
            int off = lrow * LDS + lc0;
            #pragma unroll
            for (int i = 0; i < 8; i++) {
                float hi, lo;
                split_tf32(ra[i], hi, lo); AH[nb + off + i] = hi; AL[nb + off + i] = lo;
                split_tf32(rb[i], hi, lo);
                BH[nb + (bc + 16 * i) * LDS + bkr] = hi;
                BL[nb + (bc + 16 * i) * LDS + bkr] = lo;
            }
        }
        __syncthreads();
    }

    #pragma unroll
    for (int i = 0; i < 2; i++)
        #pragma unroll
        for (int j = 0; j < 4; j++)
            wmma::store_matrix_sync(C + (size_t)(m0 + wr + i * 16) * ldc + wc + j * 16,
                                    acc[i][j], ldc, wmma::mem_row_major);
}

// ---------------- rmsnorm ----------------
__global__ void rmsnorm_rows(const float* __restrict__ x, const float* __restrict__ w,
                             float* __restrict__ y, int dim)
{
    int row = blockIdx.x;
    const float* xr = x + (size_t)row * dim;
    float ss = 0.f;
    for (int i = threadIdx.x; i < dim; i += blockDim.x) { float v = xr[i]; ss += v * v; }
    ss = blockReduceSum(ss);
    float rinv = rsqrtf(ss / dim + EPSV);
    float* yr = y + (size_t)row * dim;
    for (int i = threadIdx.x; i < dim; i += blockDim.x) yr[i] = xr[i] * rinv * w[i];
}

// ---------------- split kv -> rmsnorm(latent) + rope(k_pe) ----------------
__global__ void kv_norm_rope(const float* __restrict__ kv, const float* __restrict__ w,
                             const float* __restrict__ cosT, const float* __restrict__ sinT,
                             float* __restrict__ kvn, float* __restrict__ kpe)
{
    int s = blockIdx.x;
    const float* kr = kv + (size_t)s * (KVLR + ROPED);
    float ss = 0.f;
    for (int i = threadIdx.x; i < KVLR; i += blockDim.x) { float v = kr[i]; ss += v * v; }
    ss = blockReduceSum(ss);
    float rinv = rsqrtf(ss / KVLR + EPSV);
    for (int i = threadIdx.x; i < KVLR; i += blockDim.x)
        kvn[(size_t)s * KVLR + i] = kr[i] * rinv * w[i];
    if (threadIdx.x < ROPED / 2) {
        int i = threadIdx.x;
        float x0 = kr[KVLR + 2 * i], x1 = kr[KVLR + 2 * i + 1];
        float c = cosT[s * (ROPED / 2) + i], sn = sinT[s * (ROPED / 2) + i];
        kpe[(size_t)s * ROPED + 2 * i]     = x0 * c - x1 * sn;
        kpe[(size_t)s * ROPED + 2 * i + 1] = x0 * sn + x1 * c;
    }
}

// ---------------- rope on q_pe ----------------
__global__ void rope_q(float* __restrict__ q, const float* __restrict__ cosT,
                       const float* __restrict__ sinT)
{
    int s = blockIdx.x;
    int h = threadIdx.x >> 5;
    int i = threadIdx.x & 31;
    float* p = q + (size_t)s * QW + h * QKHD + NOPE + 2 * i;
    float x0 = p[0], x1 = p[1];
    float c = cosT[s * (ROPED / 2) + i], sn = sinT[s * (ROPED / 2) + i];
    p[0] = x0 * c - x1 * sn;
    p[1] = x0 * sn + x1 * c;
}

// ---------------- assemble K ----------------
__global__ void build_k(const float* __restrict__ kvb, const float* __restrict__ kpe,
                        float* __restrict__ k)
{
    int idx = blockIdx.x * blockDim.x + threadIdx.x;
    const int total = SEQ * NH * QKHD;
    if (idx >= total) return;
    int j  = idx % QKHD;
    int sh = idx / QKHD;
    int h  = sh % NH;
    int s  = sh / NH;
    k[idx] = (j < NOPE) ? kvb[(size_t)s * KVBW + h * (NOPE + VHD) + j]
                        : kpe[(size_t)s * ROPED + (j - NOPE)];
}

// ---------------- causal row softmax ----------------
__global__ __launch_bounds__(256)
void softmax_causal(float* __restrict__ scores)
{
    int s = blockIdx.x;
    int h = blockIdx.y;
    float* row = scores + ((size_t)h * SEQ + s) * SEQ;
    int L = s + 1;
    float v[8];
    float mx = -INFINITY;
    #pragma unroll
    for (int k = 0; k < 8; k++) {
        int t = threadIdx.x + k * 256;
        v[k] = (t < L) ? row[t] : -INFINITY;
        mx = fmaxf(mx, v[k]);
    }
    mx = blockReduceMax(mx);
    float sum = 0.f;
    #pragma unroll
    for (int k = 0; k < 8; k++) {
        int t = threadIdx.x + k * 256;
        if (t < L) { v[k] = __expf(v[k] - mx); sum += v[k]; }
        else v[k] = 0.f;
    }
    sum = blockReduceSum(sum);
    float inv = 1.f / sum;
    #pragma unroll
    for (int k = 0; k < 8; k++)
        row[threadIdx.x + k * 256] = v[k] * inv;
}

// =====================================================================
extern "C" void kernel_launch(void* const* d_in, const int* in_sizes, int n_in,
                              void* d_out, int out_size)
{
    const float* x       = (const float*)d_in[0];
    const float* cosT    = (const float*)d_in[2];
    const float* sinT    = (const float*)d_in[3];
    const float* wq_a_w  = (const float*)d_in[5];
    const float* wq_a_b  = (const float*)d_in[6];
    const float* q_nw    = (const float*)d_in[7];
    const float* wq_b_w  = (const float*)d_in[8];
    const float* wq_b_b  = (const float*)d_in[9];
    const float* wkv_a_w = (const float*)d_in[10];
    const float* wkv_a_b = (const float*)d_in[11];
    const float* kv_nw   = (const float*)d_in[12];
    const float* wkv_b_w = (const float*)d_in[13];
    const float* wkv_b_b = (const float*)d_in[14];
    const float* wo_w    = (const float*)d_in[15];
    const float* wo_b    = (const float*)d_in[16];
    float* out = (float*)d_out;

    float *qa, *q, *kv, *kvn, *kpe, *kvb, *k, *sc, *att;
    cudaGetSymbolAddress((void**)&qa,  g_qa);
    cudaGetSymbolAddress((void**)&q,   g_q);
    cudaGetSymbolAddress((void**)&kv,  g_kv);
    cudaGetSymbolAddress((void**)&kvn, g_kvn);
    cudaGetSymbolAddress((void**)&kpe, g_kpe);
    cudaGetSymbolAddress((void**)&kvb, g_kvb);
    cudaGetSymbolAddress((void**)&k,   g_k);
    cudaGetSymbolAddress((void**)&sc,  g_sc);
    cudaGetSymbolAddress((void**)&att, g_att);

    cudaFuncSetAttribute(gemm3_nt<false, false>, cudaFuncAttributeMaxDynamicSharedMemorySize, GEMM_SMEM);
    cudaFuncSetAttribute(gemm3_nt<false, true>,  cudaFuncAttributeMaxDynamicSharedMemorySize, GEMM_SMEM);
    cudaFuncSetAttribute(gemm3_nt<true,  false>, cudaFuncAttributeMaxDynamicSharedMemorySize, GEMM_SMEM);
    cudaFuncSetAttribute(gemm3_nn<true>,         cudaFuncAttributeMaxDynamicSharedMemorySize, GEMM_SMEM);

    // ---- q_a = x @ wq_a^T + b ; rmsnorm ----
    gemm3_nt<false, false><<<dim3(QLR / 128, SEQ / 128, 1), 256, GEMM_SMEM>>>(
        x, DIMM, 0, wq_a_w, DIMM, 0, wq_a_b, qa, QLR, 0, SEQ, QLR, DIMM, 1.f);
    rmsnorm_rows<<<SEQ, 256>>>(qa, q_nw, qa, QLR);

    // ---- q = qa_n @ wq_b^T + b ; rope ----
    gemm3_nt<false, false><<<dim3(QW / 128, SEQ / 128, 1), 256, GEMM_SMEM>>>(
        qa, QLR, 0, wq_b_w, QLR, 0, wq_b_b, q, QW, 0, SEQ, QW, QLR, 1.f);
    rope_q<<<SEQ, NH * 32>>>(q, cosT, sinT);

    // ---- kv = x @ wkv_a^T + b ; split/norm/rope ----
    gemm3_nt<false, true><<<dim3(5, SEQ / 128, 1), 256, GEMM_SMEM>>>(
        x, DIMM, 0, wkv_a_w, DIMM, 0, wkv_a_b, kv, KVLR + ROPED, 0,
        SEQ, KVLR + ROPED, DIMM, 1.f);
    kv_norm_rope<<<SEQ, 256>>>(kv, kv_nw, cosT, sinT, kvn, kpe);

    // ---- kvb = kvn @ wkv_b^T + b ----
    gemm3_nt<false, false><<<dim3(KVBW / 128, SEQ / 128, 1), 256, GEMM_SMEM>>>(
        kvn, KVLR, 0, wkv_b_w, KVLR, 0, wkv_b_b, kvb, KVBW, 0, SEQ, KVBW, KVLR, 1.f);

    // ---- assemble K ----
    build_k<<<(SEQ * NH * QKHD + 255) / 256, 256>>>(kvb, kpe, k);

    // ---- scores (batched over heads, causal tile-skip) ----
    gemm3_nt<true, false><<<dim3(SEQ / 128, SEQ / 128, NH), 256, GEMM_SMEM>>>(
        q, QW, QKHD, k, QW, QKHD, nullptr, sc, SEQ, (long)SEQ * SEQ,
        SEQ, SEQ, QKHD, ATTN_SCALE);

    // ---- softmax ----
    softmax_causal<<<dim3(SEQ, NH), 256>>>(sc);

    // ---- att = probs @ V (batched, causal k-limit) ----
    gemm3_nn<true><<<dim3(1, SEQ / 128, NH), 256, GEMM_SMEM>>>(
        sc, SEQ, (long)SEQ * SEQ,
        kvb + NOPE, KVBW, (long)(NOPE + VHD),
        att, NH * VHD, (long)VHD,
        SEQ, SEQ);

    // ---- out = att @ wo^T + b ----
    gemm3_nt<false, false><<<dim3(DIMM / 128, SEQ / 128, 1), 256, GEMM_SMEM>>>(
        att, NH * VHD, 0, wo_w, NH * VHD, 0, wo_b, out, DIMM, 0,
        SEQ, DIMM, NH * VHD, 1.f);
}